// round 11
// baseline (speedup 1.0000x reference)
#include <cuda_runtime.h>
#include <cuda_fp16.h>
#include <mma.h>
#include <math.h>
#include <stdint.h>

using namespace nvcuda;

#define NN 100000
#define NE 1600000
#define F 128
#define KSEL 128
#define CAND_CAP 2048
#define SCAN_BLK 25          // ceil(100000 / 4096)
#define XROWS 64
#define XLD (F + 8)          // 136 halves per smem row

typedef unsigned long long u64;

// ---------------- scratch (device globals; no allocations allowed) ----------
static __device__ unsigned int g_keys[NN];
static __device__ int          g_deg[NN];
static __device__ float        g_dinv[NN];
static __device__ int          g_rowstart[NN + 1];
static __device__ int          g_cursor[NN];
static __device__ int          g_srcrow[NE];
static __device__ int          g_bsum[32];
static __device__ int          g_boff[32];
static __device__ unsigned int g_xwh[(size_t)NN * (F / 2)];   // xw fp16 (2/uint)
static __device__ __half       g_Wh[F * F];                   // W_new fp16 [k][n]
static __device__ float        g_xt[KSEL * F];
static __device__ float        g_Wnew[F * F];
static __device__ float        g_inv_norm;
static __device__ unsigned int g_thresh;
static __device__ int          g_ncand;
static __device__ unsigned long long g_cand[CAND_CAP];
static __device__ int          g_top_idx[KSEL];
static __device__ float        g_top_gate[KSEL];

// ---------------- helpers -----------------------------------------------------
__device__ __forceinline__ unsigned int h2_to_u32(__half2 h) {
    return *reinterpret_cast<unsigned int*>(&h);
}
__device__ __forceinline__ float2 u32_to_f2(unsigned int u) {
    __half2 h = *reinterpret_cast<__half2*>(&u);
    return __half22float2(h);
}

// ---------------- prep: ||p||^-1 and counter reset ---------------------------
__global__ void k_prep(const float* __restrict__ p) {
    __shared__ float red[128];
    int t = threadIdx.x;
    float v = p[t];
    red[t] = v * v;
    __syncthreads();
    for (int s = 64; s > 0; s >>= 1) {
        if (t < s) red[t] += red[t + s];
        __syncthreads();
    }
    if (t == 0) {
        g_inv_norm = 1.0f / sqrtf(red[0]);
        g_ncand = 0;
    }
}

// ---------------- scores: warp-per-node dot(x[i], p); zero deg ---------------
__global__ void k_scores(const float* __restrict__ x, const float* __restrict__ p) {
    int gw = (blockIdx.x * blockDim.x + threadIdx.x) >> 5;
    int lane = threadIdx.x & 31;
    if (gw >= NN) return;
    float4 xv = ((const float4*)(x + (size_t)gw * F))[lane];
    float4 pv = ((const float4*)p)[lane];
    float s = xv.x * pv.x + xv.y * pv.y + xv.z * pv.z + xv.w * pv.w;
    #pragma unroll
    for (int off = 16; off > 0; off >>= 1)
        s += __shfl_xor_sync(0xFFFFFFFFu, s, off);
    if (lane == 0) {
        // selection order invariant to positive scale 1/||p||; applied at gate.
        unsigned int b = __float_as_uint(s);
        unsigned int u = (b & 0x80000000u) ? ~b : (b | 0x80000000u);
        g_keys[gw] = u;
        g_deg[gw] = 0;
    }
}

// ---------------- exact 128th-largest key via 4x8-bit radix select -----------
__global__ void k_radix() {
    __shared__ unsigned int hist[256];
    __shared__ unsigned int s_prefix;
    __shared__ unsigned int s_krem;
    if (threadIdx.x == 0) { s_prefix = 0u; s_krem = KSEL; }
    for (int shift = 24; shift >= 0; shift -= 8) {
        if (threadIdx.x < 256) hist[threadIdx.x] = 0u;
        __syncthreads();
        unsigned int prefix = s_prefix;
        unsigned int maskhi = (shift == 24) ? 0u : (0xFFFFFFFFu << (shift + 8));
        for (int i = threadIdx.x; i < NN; i += blockDim.x) {
            unsigned int k = g_keys[i];
            if ((k & maskhi) == prefix)
                atomicAdd(&hist[(k >> shift) & 0xFFu], 1u);
        }
        __syncthreads();
        if (threadIdx.x == 0) {
            unsigned int cum = 0, krem = s_krem;
            int b = 255;
            for (; b >= 0; b--) {
                if (cum + hist[b] >= krem) break;
                cum += hist[b];
            }
            if (b < 0) b = 0;
            s_krem = krem - cum;
            s_prefix = prefix | ((unsigned int)b << shift);
        }
        __syncthreads();
    }
    if (threadIdx.x == 0) g_thresh = s_prefix;
}

// ---------------- collect candidates with key >= threshold -------------------
__global__ void k_collect() {
    int i = blockIdx.x * blockDim.x + threadIdx.x;
    if (i >= NN) return;
    unsigned int u = g_keys[i];
    if (u >= g_thresh) {
        int pos = atomicAdd(&g_ncand, 1);
        if (pos < CAND_CAP)
            g_cand[pos] = ((unsigned long long)u << 32)
                        | (unsigned long long)(0xFFFFFFFFu - (unsigned int)i);
    }
}

// ---------------- sort candidates desc (key, then idx asc), emit top-128 -----
__global__ void k_sort() {
    __shared__ unsigned long long s[CAND_CAP];
    __shared__ int sm_m;
    int tid = threadIdx.x;
    int n = g_ncand; if (n > CAND_CAP) n = CAND_CAP;
    if (tid == 0) {
        int m = 256;
        while (m < n) m <<= 1;
        sm_m = m;
    }
    __syncthreads();
    int m = sm_m;
    for (int i = tid; i < m; i += blockDim.x)
        s[i] = (i < n) ? g_cand[i] : 0ull;
    __syncthreads();
    for (int k = 2; k <= m; k <<= 1) {
        for (int j = k >> 1; j > 0; j >>= 1) {
            for (int i = tid; i < m; i += blockDim.x) {
                int ixj = i ^ j;
                if (ixj > i) {
                    bool desc = ((i & k) == 0);
                    unsigned long long a = s[i], b = s[ixj];
                    bool swap = desc ? (a < b) : (a > b);
                    if (swap) { s[i] = b; s[ixj] = a; }
                }
            }
            __syncthreads();
        }
    }
    if (tid < KSEL) {
        unsigned long long v = s[tid];
        unsigned int u = (unsigned int)(v >> 32);
        int idx = (int)(0xFFFFFFFFu - (unsigned int)(v & 0xFFFFFFFFu));
        unsigned int b = (u & 0x80000000u) ? (u & 0x7FFFFFFFu) : ~u;
        float sc = __uint_as_float(b) * g_inv_norm;   // apply 1/||p|| here
        g_top_idx[tid] = idx;
        g_top_gate[tid] = tanhf(sc);
    }
}

// ---------------- x_tilde[j] = x[top_idx[j]] * tanh(top_val[j]) --------------
__global__ void k_xtilde(const float* __restrict__ x) {
    int j = blockIdx.x, c = threadIdx.x;
    int idx = g_top_idx[j];
    float gate = g_top_gate[j];
    g_xt[j * F + c] = x[(size_t)idx * F + c] * gate;
}

// ---------------- GRU step: W_new -------------------------------------------
__global__ void k_gru(const float* __restrict__ W,
                      const float* __restrict__ w_ih, const float* __restrict__ w_hh,
                      const float* __restrict__ b_ih, const float* __restrict__ b_hh) {
    int r = blockIdx.x, c = threadIdx.x;
    __shared__ float xt[F];
    __shared__ float wr[F];
    xt[c] = g_xt[r * F + c];
    wr[c] = W[r * F + c];
    __syncthreads();
    const float* wi0 = w_ih + (size_t)c * F;
    const float* wi1 = w_ih + (size_t)(F + c) * F;
    const float* wi2 = w_ih + (size_t)(2 * F + c) * F;
    const float* wh0 = w_hh + (size_t)c * F;
    const float* wh1 = w_hh + (size_t)(F + c) * F;
    const float* wh2 = w_hh + (size_t)(2 * F + c) * F;
    float gi0 = 0.f, gi1 = 0.f, gi2 = 0.f, gh0 = 0.f, gh1 = 0.f, gh2 = 0.f;
    #pragma unroll 8
    for (int k = 0; k < F; k++) {
        float xk = xt[k], wk = wr[k];
        gi0 += xk * __ldg(wi0 + k);
        gi1 += xk * __ldg(wi1 + k);
        gi2 += xk * __ldg(wi2 + k);
        gh0 += wk * __ldg(wh0 + k);
        gh1 += wk * __ldg(wh1 + k);
        gh2 += wk * __ldg(wh2 + k);
    }
    gi0 += b_ih[c];         gh0 += b_hh[c];
    gi1 += b_ih[F + c];     gh1 += b_hh[F + c];
    gi2 += b_ih[2 * F + c]; gh2 += b_hh[2 * F + c];
    float rg = 1.f / (1.f + expf(-(gi0 + gh0)));
    float z  = 1.f / (1.f + expf(-(gi1 + gh1)));
    float nn = tanhf(gi2 + rg * gh2);
    g_Wnew[r * F + c] = (1.f - z) * nn + z * wr[c];
}

// ---------------- convert W_new to fp16 --------------------------------------
__global__ void k_wh() {
    int i = blockIdx.x * blockDim.x + threadIdx.x;
    if (i < F * F) g_Wh[i] = __float2half(g_Wnew[i]);
}

// ---------------- degree count ----------------------------------------------
__global__ void k_degcnt(const int* __restrict__ ei) {
    int e = blockIdx.x * blockDim.x + threadIdx.x;
    if (e >= NE) return;
    atomicAdd(&g_deg[ei[NE + e]], 1);
}

// ---------------- 3-kernel exclusive prefix scan of degrees ------------------
__global__ void k_scan1() {
    __shared__ int ssum[1024];
    int bid = blockIdx.x, t = threadIdx.x;
    int base = bid * 4096 + t * 4;
    int v[4]; int s = 0;
    #pragma unroll
    for (int j = 0; j < 4; j++) {
        int idx = base + j;
        v[j] = (idx < NN) ? g_deg[idx] : 0;
        s += v[j];
    }
    ssum[t] = s;
    __syncthreads();
    for (int off = 1; off < 1024; off <<= 1) {
        int xv = (t >= off) ? ssum[t - off] : 0;
        __syncthreads();
        ssum[t] += xv;
        __syncthreads();
    }
    int run = ssum[t] - s;   // exclusive within block
    if (t == 1023) g_bsum[bid] = ssum[1023];
    #pragma unroll
    for (int j = 0; j < 4; j++) {
        int idx = base + j;
        if (idx < NN) g_rowstart[idx] = run;
        run += v[j];
    }
}

__global__ void k_scan2() {
    int t = threadIdx.x;
    int v = (t < SCAN_BLK) ? g_bsum[t] : 0;
    int orig = v;
    #pragma unroll
    for (int off = 1; off < 32; off <<= 1) {
        int u = __shfl_up_sync(0xFFFFFFFFu, v, off);
        if (t >= off) v += u;
    }
    g_boff[t] = v - orig;    // exclusive
}

__global__ void k_scan3() {
    int i = blockIdx.x * blockDim.x + threadIdx.x;
    if (i >= NN) return;
    int r = g_rowstart[i] + g_boff[i >> 12];
    g_rowstart[i] = r;
    g_cursor[i] = r;
    g_dinv[i] = rsqrtf((float)g_deg[i] + 1.0f);
    if (i == 0) g_rowstart[NN] = NE;
}

// ---------------- fill CSR: srcrow bucketed by col ---------------------------
__global__ void k_fill(const int* __restrict__ ei) {
    int e = blockIdx.x * blockDim.x + threadIdx.x;
    if (e >= NE) return;
    int row = __ldg(ei + e);
    int col = __ldg(ei + NE + e);
    int pos = atomicAdd(&g_cursor[col], 1);
    g_srcrow[pos] = row;
}

// ---------------- xw = x @ W_new via wmma (fp16 in, fp32 acc, fp16 out) ------
// block: 256 threads = 8 warps; tile 64 rows x 128 cols.
// warp w: rows (w&3)*16..+16, cols (w>>2)*64..+64 (4 wmma n-subtiles).
__global__ void __launch_bounds__(256) k_xw(const float* __restrict__ x) {
    extern __shared__ char smem_raw[];
    __half* xs = (__half*)smem_raw;            // [XROWS][XLD] = 17408 B
    float*  os = (float*)smem_raw;             // [XROWS][F]   = 32768 B (reuse)
    int tid = threadIdx.x;
    int wid = tid >> 5;
    int row0 = blockIdx.x * XROWS;

    // load + convert x tile to fp16 smem
    for (int i = tid; i < XROWS * (F / 4); i += 256) {
        int r = i >> 5;           // 32 float4 per row
        int q = i & 31;
        int gr = row0 + r;
        float4 v = (gr < NN) ? ((const float4*)x)[(size_t)gr * 32 + q]
                             : make_float4(0.f, 0.f, 0.f, 0.f);
        __half2* dst = (__half2*)&xs[r * XLD + q * 4];
        dst[0] = __floats2half2_rn(v.x, v.y);
        dst[1] = __floats2half2_rn(v.z, v.w);
    }
    __syncthreads();

    int m0 = (wid & 3) * 16;
    int n0 = (wid >> 2) * 64;
    wmma::fragment<wmma::accumulator, 16, 16, 16, float> c[4];
    #pragma unroll
    for (int t = 0; t < 4; t++) wmma::fill_fragment(c[t], 0.0f);
    #pragma unroll
    for (int k0 = 0; k0 < F; k0 += 16) {
        wmma::fragment<wmma::matrix_a, 16, 16, 16, __half, wmma::row_major> a;
        wmma::load_matrix_sync(a, &xs[m0 * XLD + k0], XLD);
        #pragma unroll
        for (int t = 0; t < 4; t++) {
            wmma::fragment<wmma::matrix_b, 16, 16, 16, __half, wmma::row_major> b;
            wmma::load_matrix_sync(b, &g_Wh[k0 * F + n0 + t * 16], F);
            wmma::mma_sync(c[t], a, b, c[t]);
        }
    }
    __syncthreads();   // xs fully consumed; reuse smem as float out
    #pragma unroll
    for (int t = 0; t < 4; t++)
        wmma::store_matrix_sync(&os[m0 * F + n0 + t * 16], c[t], F, wmma::mem_row_major);
    __syncthreads();

    // convert to fp16 and store
    for (int i = tid; i < XROWS * (F / 4); i += 256) {
        int r = i >> 5, q = i & 31;
        int gr = row0 + r;
        if (gr < NN) {
            float4 v = ((const float4*)&os[r * F])[q];
            uint2 u;
            u.x = h2_to_u32(__floats2half2_rn(v.x, v.y));
            u.y = h2_to_u32(__floats2half2_rn(v.z, v.w));
            ((uint2*)(g_xwh + (size_t)gr * (F / 2)))[q] = u;
        }
    }
}

// ---------------- fused gather + self-loop + relu + head ---------------------
// warp per node, fp16 xw rows, fp32 accumulate, 4x-unrolled edge loop (MLP=4)
__global__ void k_gather(const float* __restrict__ conv_bias,
                         const float* __restrict__ lin_w,
                         const float* __restrict__ lin_b,
                         float* __restrict__ out) {
    int gw = (blockIdx.x * blockDim.x + threadIdx.x) >> 5;
    int lane = threadIdx.x & 31;
    if (gw >= NN) return;
    int s = g_rowstart[gw];
    int e = g_rowstart[gw + 1];
    float di = g_dinv[gw];
    float s2 = di * di;
    float4 acc;
    {
        uint2 raw = ((const uint2*)(g_xwh + (size_t)gw * (F / 2)))[lane];
        float2 f0 = u32_to_f2(raw.x);
        float2 f1 = u32_to_f2(raw.y);
        float4 b = ((const float4*)conv_bias)[lane];
        acc.x = f0.x * s2 + b.x; acc.y = f0.y * s2 + b.y;
        acc.z = f1.x * s2 + b.z; acc.w = f1.y * s2 + b.w;
    }
    for (int base = s; base < e; base += 32) {
        int idx = base + lane;
        int r = 0; float dr = 0.f;
        if (idx < e) {
            r = __ldg(g_srcrow + idx);
            dr = __ldg(g_dinv + r);
        }
        int n = min(32, e - base);
        int j = 0;
        for (; j + 4 <= n; j += 4) {
            int r0 = __shfl_sync(0xFFFFFFFFu, r, j);
            int r1 = __shfl_sync(0xFFFFFFFFu, r, j + 1);
            int r2 = __shfl_sync(0xFFFFFFFFu, r, j + 2);
            int r3 = __shfl_sync(0xFFFFFFFFu, r, j + 3);
            float c0 = __shfl_sync(0xFFFFFFFFu, dr, j)     * di;
            float c1 = __shfl_sync(0xFFFFFFFFu, dr, j + 1) * di;
            float c2 = __shfl_sync(0xFFFFFFFFu, dr, j + 2) * di;
            float c3 = __shfl_sync(0xFFFFFFFFu, dr, j + 3) * di;
            uint2 w0 = __ldg((const uint2*)(g_xwh + (size_t)r0 * (F / 2)) + lane);
            uint2 w1 = __ldg((const uint2*)(g_xwh + (size_t)r1 * (F / 2)) + lane);
            uint2 w2 = __ldg((const uint2*)(g_xwh + (size_t)r2 * (F / 2)) + lane);
            uint2 w3 = __ldg((const uint2*)(g_xwh + (size_t)r3 * (F / 2)) + lane);
            float2 a0 = u32_to_f2(w0.x), b0 = u32_to_f2(w0.y);
            float2 a1 = u32_to_f2(w1.x), b1 = u32_to_f2(w1.y);
            float2 a2 = u32_to_f2(w2.x), b2 = u32_to_f2(w2.y);
            float2 a3 = u32_to_f2(w3.x), b3 = u32_to_f2(w3.y);
            acc.x += a0.x * c0; acc.y += a0.y * c0; acc.z += b0.x * c0; acc.w += b0.y * c0;
            acc.x += a1.x * c1; acc.y += a1.y * c1; acc.z += b1.x * c1; acc.w += b1.y * c1;
            acc.x += a2.x * c2; acc.y += a2.y * c2; acc.z += b2.x * c2; acc.w += b2.y * c2;
            acc.x += a3.x * c3; acc.y += a3.y * c3; acc.z += b3.x * c3; acc.w += b3.y * c3;
        }
        for (; j < n; j++) {
            int row = __shfl_sync(0xFFFFFFFFu, r, j);
            float c = __shfl_sync(0xFFFFFFFFu, dr, j) * di;
            uint2 raw = __ldg((const uint2*)(g_xwh + (size_t)row * (F / 2)) + lane);
            float2 f0 = u32_to_f2(raw.x);
            float2 f1 = u32_to_f2(raw.y);
            acc.x += f0.x * c; acc.y += f0.y * c;
            acc.z += f1.x * c; acc.w += f1.y * c;
        }
    }
    float4 lw = ((const float4*)lin_w)[lane];
    float pr = fmaxf(acc.x, 0.f) * lw.x + fmaxf(acc.y, 0.f) * lw.y
             + fmaxf(acc.z, 0.f) * lw.z + fmaxf(acc.w, 0.f) * lw.w;
    #pragma unroll
    for (int off = 16; off > 0; off >>= 1)
        pr += __shfl_xor_sync(0xFFFFFFFFu, pr, off);
    if (lane == 0) out[gw] = pr + lin_b[0];
}

// ---------------- launcher ---------------------------------------------------
extern "C" void kernel_launch(void* const* d_in, const int* in_sizes, int n_in,
                              void* d_out, int out_size) {
    const float* x         = (const float*)d_in[0];
    const int*   ei        = (const int*)d_in[1];
    const float* W         = (const float*)d_in[2];
    const float* p         = (const float*)d_in[3];
    const float* w_ih      = (const float*)d_in[4];
    const float* w_hh      = (const float*)d_in[5];
    const float* b_ih      = (const float*)d_in[6];
    const float* b_hh      = (const float*)d_in[7];
    const float* conv_bias = (const float*)d_in[8];
    const float* lin_w     = (const float*)d_in[9];
    const float* lin_b     = (const float*)d_in[10];
    float* out = (float*)d_out;

    k_prep<<<1, 128>>>(p);
    k_scores<<<(NN * 32 + 255) / 256, 256>>>(x, p);
    k_radix<<<1, 1024>>>();
    k_collect<<<(NN + 255) / 256, 256>>>();
    k_sort<<<1, 256>>>();
    k_xtilde<<<KSEL, F>>>(x);
    k_gru<<<F, F>>>(W, w_ih, w_hh, b_ih, b_hh);
    k_wh<<<(F * F + 255) / 256, 256>>>();
    k_degcnt<<<(NE + 255) / 256, 256>>>(ei);
    k_scan1<<<SCAN_BLK, 1024>>>();
    k_scan2<<<1, 32>>>();
    k_scan3<<<(NN + 255) / 256, 256>>>();
    k_fill<<<(NE + 255) / 256, 256>>>(ei);
    k_xw<<<(NN + XROWS - 1) / XROWS, 256, 32768>>>(x);
    k_gather<<<(NN * 32 + 255) / 256, 256>>>(conv_bias, lin_w, lin_b, out);
}

// round 12
// speedup vs baseline: 1.1011x; 1.1011x over previous
#include <cuda_runtime.h>
#include <cuda_fp16.h>
#include <mma.h>
#include <math.h>
#include <stdint.h>

using namespace nvcuda;

#define NN 100000
#define NE 1600000
#define F 128
#define KSEL 128
#define CAND_CAP 2048
#define SCAN_BLK 25          // ceil(100000 / 4096)
#define XROWS 64
#define XLD (F + 8)          // 136 halves per smem row
#define HBINS 32768

typedef unsigned long long u64;

// ---------------- scratch (device globals; no allocations allowed) ----------
static __device__ unsigned int g_keys[NN];
static __device__ int          g_deg[NN];
static __device__ float        g_dinv[NN];
static __device__ int          g_rowstart[NN + 1];
static __device__ int          g_cursor[NN];
static __device__ int          g_srcrow[NE];
static __device__ int          g_bsum[32];
static __device__ int          g_boff[32];
static __device__ int          g_hist[HBINS];
static __device__ unsigned int g_xwh[(size_t)NN * (F / 2)];   // xw fp16 (2/uint)
static __device__ __half       g_Wh[F * F];                   // W_new fp16 [k][n]
static __device__ float        g_inv_norm;
static __device__ unsigned int g_thresh;
static __device__ int          g_ncand;
static __device__ unsigned long long g_cand[CAND_CAP];
static __device__ int          g_top_idx[KSEL];
static __device__ float        g_top_gate[KSEL];

// ---------------- helpers -----------------------------------------------------
__device__ __forceinline__ unsigned int h2_to_u32(__half2 h) {
    return *reinterpret_cast<unsigned int*>(&h);
}
__device__ __forceinline__ float2 u32_to_f2(unsigned int u) {
    __half2 h = *reinterpret_cast<__half2*>(&u);
    return __half22float2(h);
}

// ---------------- prep: zero hist + deg, ||p||^-1, counter reset -------------
__global__ void k_prep(const float* __restrict__ p) {
    int tid = blockIdx.x * blockDim.x + threadIdx.x;
    int stride = gridDim.x * blockDim.x;
    for (int i = tid; i < HBINS; i += stride) g_hist[i] = 0;
    for (int i = tid; i < NN; i += stride) g_deg[i] = 0;
    if (blockIdx.x == 0) {
        __shared__ float red[128];
        int t = threadIdx.x;
        if (t < 128) { float v = p[t]; red[t] = v * v; }
        __syncthreads();
        for (int s = 64; s > 0; s >>= 1) {
            if (t < s) red[t] += red[t + s];
            __syncthreads();
        }
        if (t == 0) {
            g_inv_norm = rsqrtf(red[0]);
            g_ncand = 0;
        }
    }
}

// ---------------- scores (warp/node) + hist + degree count -------------------
__global__ void k_scores(const float* __restrict__ x, const int* __restrict__ ei) {
    int gw = (blockIdx.x * blockDim.x + threadIdx.x) >> 5;
    int lane = threadIdx.x & 31;
    if (gw < NN) {
        float4 xv = ((const float4*)(x + (size_t)gw * F))[lane];
        // p-vector via lane-wide broadcast of x row dot p: need p — removed;
        // score uses unnormalized dot(x, p) — but p not passed; see below.
        // (handled by second param trick: p rows appended) -- NOT USED
        (void)xv;
    }
    // NOTE: real work below (restructured to keep p accessible)
    // -- this placeholder exists only to keep structure clear --
    // (actual implementation in k_scores2)
    // degree count: grid-stride over edges
    int gtid = blockIdx.x * blockDim.x + threadIdx.x;
    int stride = gridDim.x * blockDim.x;
    for (int e = gtid; e < NE; e += stride)
        atomicAdd(&g_deg[__ldg(ei + NE + e)], 1);
    (void)lane;
}

// real scores kernel (keeps p): warp-per-node dot + hist atomic
__global__ void k_scores2(const float* __restrict__ x, const float* __restrict__ p,
                          const int* __restrict__ ei) {
    int gw = (blockIdx.x * blockDim.x + threadIdx.x) >> 5;
    int lane = threadIdx.x & 31;
    if (gw < NN) {
        float4 xv = ((const float4*)(x + (size_t)gw * F))[lane];
        float4 pv = ((const float4*)p)[lane];
        float s = xv.x * pv.x + xv.y * pv.y + xv.z * pv.z + xv.w * pv.w;
        #pragma unroll
        for (int off = 16; off > 0; off >>= 1)
            s += __shfl_xor_sync(0xFFFFFFFFu, s, off);
        if (lane == 0) {
            // selection order invariant to positive scale 1/||p||; applied at gate.
            unsigned int b = __float_as_uint(s);
            unsigned int u = (b & 0x80000000u) ? ~b : (b | 0x80000000u);
            g_keys[gw] = u;
            atomicAdd(&g_hist[u >> 17], 1);
        }
    }
    // fused degree count: grid-stride over edges
    int gtid = blockIdx.x * blockDim.x + threadIdx.x;
    int stride = gridDim.x * blockDim.x;
    for (int e = gtid; e < NE; e += stride)
        atomicAdd(&g_deg[__ldg(ei + NE + e)], 1);
}

// ---------------- pick: bin containing the 128th largest key -----------------
__global__ void k_pick() {
    __shared__ int ssum[1024];
    int t = threadIdx.x;
    int base = t * 32;
    int s = 0;
    #pragma unroll 8
    for (int j = 0; j < 32; j++) s += g_hist[base + j];
    ssum[t] = s;
    __syncthreads();
    // inclusive suffix scan: ssum[t] = sum_{j>=t} s_j
    for (int off = 1; off < 1024; off <<= 1) {
        int v = (t + off < 1024) ? ssum[t + off] : 0;
        __syncthreads();
        ssum[t] += v;
        __syncthreads();
    }
    int above = (t < 1023) ? ssum[t + 1] : 0;   // keys in higher chunks
    if (above < KSEL && ssum[t] >= KSEL) {
        // threshold bin lies inside this thread's chunk
        int cum = above;
        for (int b = base + 31; b >= base; b--) {
            cum += g_hist[b];
            if (cum >= KSEL) {
                g_thresh = ((unsigned int)b) << 17;   // bin floor
                break;
            }
        }
    }
}

// ---------------- collect candidates with key >= threshold -------------------
__global__ void k_collect() {
    int i = blockIdx.x * blockDim.x + threadIdx.x;
    if (i >= NN) return;
    unsigned int u = g_keys[i];
    if (u >= g_thresh) {
        int pos = atomicAdd(&g_ncand, 1);
        if (pos < CAND_CAP)
            g_cand[pos] = ((unsigned long long)u << 32)
                        | (unsigned long long)(0xFFFFFFFFu - (unsigned int)i);
    }
}

// ---------------- sort candidates desc (key, then idx asc), emit top-128 -----
__global__ void k_sort() {
    __shared__ unsigned long long s[CAND_CAP];
    __shared__ int sm_m;
    int tid = threadIdx.x;
    int n = g_ncand; if (n > CAND_CAP) n = CAND_CAP;
    if (tid == 0) {
        int m = 256;
        while (m < n) m <<= 1;
        sm_m = m;
    }
    __syncthreads();
    int m = sm_m;
    for (int i = tid; i < m; i += blockDim.x)
        s[i] = (i < n) ? g_cand[i] : 0ull;
    __syncthreads();
    for (int k = 2; k <= m; k <<= 1) {
        for (int j = k >> 1; j > 0; j >>= 1) {
            for (int i = tid; i < m; i += blockDim.x) {
                int ixj = i ^ j;
                if (ixj > i) {
                    bool desc = ((i & k) == 0);
                    unsigned long long a = s[i], b = s[ixj];
                    bool swap = desc ? (a < b) : (a > b);
                    if (swap) { s[i] = b; s[ixj] = a; }
                }
            }
            __syncthreads();
        }
    }
    if (tid < KSEL) {
        unsigned long long v = s[tid];
        unsigned int u = (unsigned int)(v >> 32);
        int idx = (int)(0xFFFFFFFFu - (unsigned int)(v & 0xFFFFFFFFu));
        unsigned int b = (u & 0x80000000u) ? (u & 0x7FFFFFFFu) : ~u;
        float sc = __uint_as_float(b) * g_inv_norm;   // apply 1/||p|| here
        g_top_idx[tid] = idx;
        g_top_gate[tid] = tanhf(sc);
    }
}

// ---------------- GRU step (fused x_tilde + fp16 W_new output) ---------------
__global__ void k_gru(const float* __restrict__ x, const float* __restrict__ W,
                      const float* __restrict__ w_ih, const float* __restrict__ w_hh,
                      const float* __restrict__ b_ih, const float* __restrict__ b_hh) {
    int r = blockIdx.x, c = threadIdx.x;
    __shared__ float xt[F];
    __shared__ float wr[F];
    {
        int idx = g_top_idx[r];
        float gate = g_top_gate[r];
        xt[c] = x[(size_t)idx * F + c] * gate;
        wr[c] = W[r * F + c];
    }
    __syncthreads();
    const float* wi0 = w_ih + (size_t)c * F;
    const float* wi1 = w_ih + (size_t)(F + c) * F;
    const float* wi2 = w_ih + (size_t)(2 * F + c) * F;
    const float* wh0 = w_hh + (size_t)c * F;
    const float* wh1 = w_hh + (size_t)(F + c) * F;
    const float* wh2 = w_hh + (size_t)(2 * F + c) * F;
    float gi0 = 0.f, gi1 = 0.f, gi2 = 0.f, gh0 = 0.f, gh1 = 0.f, gh2 = 0.f;
    #pragma unroll 8
    for (int k = 0; k < F; k++) {
        float xk = xt[k], wk = wr[k];
        gi0 += xk * __ldg(wi0 + k);
        gi1 += xk * __ldg(wi1 + k);
        gi2 += xk * __ldg(wi2 + k);
        gh0 += wk * __ldg(wh0 + k);
        gh1 += wk * __ldg(wh1 + k);
        gh2 += wk * __ldg(wh2 + k);
    }
    gi0 += b_ih[c];         gh0 += b_hh[c];
    gi1 += b_ih[F + c];     gh1 += b_hh[F + c];
    gi2 += b_ih[2 * F + c]; gh2 += b_hh[2 * F + c];
    float rg = 1.f / (1.f + expf(-(gi0 + gh0)));
    float z  = 1.f / (1.f + expf(-(gi1 + gh1)));
    float nn = tanhf(gi2 + rg * gh2);
    float wnew = (1.f - z) * nn + z * wr[c];
    g_Wh[r * F + c] = __float2half(wnew);
}

// ---------------- 3-kernel exclusive prefix scan of degrees ------------------
__global__ void k_scan1() {
    __shared__ int ssum[1024];
    int bid = blockIdx.x, t = threadIdx.x;
    int base = bid * 4096 + t * 4;
    int v[4]; int s = 0;
    #pragma unroll
    for (int j = 0; j < 4; j++) {
        int idx = base + j;
        v[j] = (idx < NN) ? g_deg[idx] : 0;
        s += v[j];
    }
    ssum[t] = s;
    __syncthreads();
    for (int off = 1; off < 1024; off <<= 1) {
        int xv = (t >= off) ? ssum[t - off] : 0;
        __syncthreads();
        ssum[t] += xv;
        __syncthreads();
    }
    int run = ssum[t] - s;   // exclusive within block
    if (t == 1023) g_bsum[bid] = ssum[1023];
    #pragma unroll
    for (int j = 0; j < 4; j++) {
        int idx = base + j;
        if (idx < NN) g_rowstart[idx] = run;
        run += v[j];
    }
}

__global__ void k_scan2() {
    int t = threadIdx.x;
    int v = (t < SCAN_BLK) ? g_bsum[t] : 0;
    int orig = v;
    #pragma unroll
    for (int off = 1; off < 32; off <<= 1) {
        int u = __shfl_up_sync(0xFFFFFFFFu, v, off);
        if (t >= off) v += u;
    }
    g_boff[t] = v - orig;    // exclusive
}

__global__ void k_scan3() {
    int i = blockIdx.x * blockDim.x + threadIdx.x;
    if (i >= NN) return;
    int r = g_rowstart[i] + g_boff[i >> 12];
    g_rowstart[i] = r;
    g_cursor[i] = r;
    g_dinv[i] = rsqrtf((float)g_deg[i] + 1.0f);
    if (i == 0) g_rowstart[NN] = NE;
}

// ---------------- fill CSR: srcrow bucketed by col ---------------------------
__global__ void k_fill(const int* __restrict__ ei) {
    int e = blockIdx.x * blockDim.x + threadIdx.x;
    if (e >= NE) return;
    int row = __ldg(ei + e);
    int col = __ldg(ei + NE + e);
    int pos = atomicAdd(&g_cursor[col], 1);
    g_srcrow[pos] = row;
}

// ---------------- xw = x @ W_new via wmma (fp16 in, fp32 acc, fp16 out) ------
__global__ void __launch_bounds__(256) k_xw(const float* __restrict__ x) {
    extern __shared__ char smem_raw[];
    __half* xs = (__half*)smem_raw;            // [XROWS][XLD] = 17408 B
    float*  os = (float*)smem_raw;             // [XROWS][F]   = 32768 B (reuse)
    int tid = threadIdx.x;
    int wid = tid >> 5;
    int row0 = blockIdx.x * XROWS;

    for (int i = tid; i < XROWS * (F / 4); i += 256) {
        int r = i >> 5;
        int q = i & 31;
        int gr = row0 + r;
        float4 v = (gr < NN) ? ((const float4*)x)[(size_t)gr * 32 + q]
                             : make_float4(0.f, 0.f, 0.f, 0.f);
        __half2* dst = (__half2*)&xs[r * XLD + q * 4];
        dst[0] = __floats2half2_rn(v.x, v.y);
        dst[1] = __floats2half2_rn(v.z, v.w);
    }
    __syncthreads();

    int m0 = (wid & 3) * 16;
    int n0 = (wid >> 2) * 64;
    wmma::fragment<wmma::accumulator, 16, 16, 16, float> c[4];
    #pragma unroll
    for (int t = 0; t < 4; t++) wmma::fill_fragment(c[t], 0.0f);
    #pragma unroll
    for (int k0 = 0; k0 < F; k0 += 16) {
        wmma::fragment<wmma::matrix_a, 16, 16, 16, __half, wmma::row_major> a;
        wmma::load_matrix_sync(a, &xs[m0 * XLD + k0], XLD);
        #pragma unroll
        for (int t = 0; t < 4; t++) {
            wmma::fragment<wmma::matrix_b, 16, 16, 16, __half, wmma::row_major> b;
            wmma::load_matrix_sync(b, &g_Wh[k0 * F + n0 + t * 16], F);
            wmma::mma_sync(c[t], a, b, c[t]);
        }
    }
    __syncthreads();
    #pragma unroll
    for (int t = 0; t < 4; t++)
        wmma::store_matrix_sync(&os[m0 * F + n0 + t * 16], c[t], F, wmma::mem_row_major);
    __syncthreads();

    for (int i = tid; i < XROWS * (F / 4); i += 256) {
        int r = i >> 5, q = i & 31;
        int gr = row0 + r;
        if (gr < NN) {
            float4 v = ((const float4*)&os[r * F])[q];
            uint2 u;
            u.x = h2_to_u32(__floats2half2_rn(v.x, v.y));
            u.y = h2_to_u32(__floats2half2_rn(v.z, v.w));
            ((uint2*)(g_xwh + (size_t)gr * (F / 2)))[q] = u;
        }
    }
}

// ---------------- fused gather + self-loop + relu + head ---------------------
__global__ void k_gather(const float* __restrict__ conv_bias,
                         const float* __restrict__ lin_w,
                         const float* __restrict__ lin_b,
                         float* __restrict__ out) {
    int gw = (blockIdx.x * blockDim.x + threadIdx.x) >> 5;
    int lane = threadIdx.x & 31;
    if (gw >= NN) return;
    int s = g_rowstart[gw];
    int e = g_rowstart[gw + 1];
    float di = g_dinv[gw];
    float s2 = di * di;
    float4 acc;
    {
        uint2 raw = ((const uint2*)(g_xwh + (size_t)gw * (F / 2)))[lane];
        float2 f0 = u32_to_f2(raw.x);
        float2 f1 = u32_to_f2(raw.y);
        float4 b = ((const float4*)conv_bias)[lane];
        acc.x = f0.x * s2 + b.x; acc.y = f0.y * s2 + b.y;
        acc.z = f1.x * s2 + b.z; acc.w = f1.y * s2 + b.w;
    }
    for (int base = s; base < e; base += 32) {
        int idx = base + lane;
        int r = 0; float dr = 0.f;
        if (idx < e) {
            r = __ldg(g_srcrow + idx);
            dr = __ldg(g_dinv + r);
        }
        int n = min(32, e - base);
        int j = 0;
        for (; j + 4 <= n; j += 4) {
            int r0 = __shfl_sync(0xFFFFFFFFu, r, j);
            int r1 = __shfl_sync(0xFFFFFFFFu, r, j + 1);
            int r2 = __shfl_sync(0xFFFFFFFFu, r, j + 2);
            int r3 = __shfl_sync(0xFFFFFFFFu, r, j + 3);
            float c0 = __shfl_sync(0xFFFFFFFFu, dr, j)     * di;
            float c1 = __shfl_sync(0xFFFFFFFFu, dr, j + 1) * di;
            float c2 = __shfl_sync(0xFFFFFFFFu, dr, j + 2) * di;
            float c3 = __shfl_sync(0xFFFFFFFFu, dr, j + 3) * di;
            uint2 w0 = __ldg((const uint2*)(g_xwh + (size_t)r0 * (F / 2)) + lane);
            uint2 w1 = __ldg((const uint2*)(g_xwh + (size_t)r1 * (F / 2)) + lane);
            uint2 w2 = __ldg((const uint2*)(g_xwh + (size_t)r2 * (F / 2)) + lane);
            uint2 w3 = __ldg((const uint2*)(g_xwh + (size_t)r3 * (F / 2)) + lane);
            float2 a0 = u32_to_f2(w0.x), b0 = u32_to_f2(w0.y);
            float2 a1 = u32_to_f2(w1.x), b1 = u32_to_f2(w1.y);
            float2 a2 = u32_to_f2(w2.x), b2 = u32_to_f2(w2.y);
            float2 a3 = u32_to_f2(w3.x), b3 = u32_to_f2(w3.y);
            acc.x += a0.x * c0; acc.y += a0.y * c0; acc.z += b0.x * c0; acc.w += b0.y * c0;
            acc.x += a1.x * c1; acc.y += a1.y * c1; acc.z += b1.x * c1; acc.w += b1.y * c1;
            acc.x += a2.x * c2; acc.y += a2.y * c2; acc.z += b2.x * c2; acc.w += b2.y * c2;
            acc.x += a3.x * c3; acc.y += a3.y * c3; acc.z += b3.x * c3; acc.w += b3.y * c3;
        }
        for (; j < n; j++) {
            int row = __shfl_sync(0xFFFFFFFFu, r, j);
            float c = __shfl_sync(0xFFFFFFFFu, dr, j) * di;
            uint2 raw = __ldg((const uint2*)(g_xwh + (size_t)row * (F / 2)) + lane);
            float2 f0 = u32_to_f2(raw.x);
            float2 f1 = u32_to_f2(raw.y);
            acc.x += f0.x * c; acc.y += f0.y * c;
            acc.z += f1.x * c; acc.w += f1.y * c;
        }
    }
    float4 lw = ((const float4*)lin_w)[lane];
    float pr = fmaxf(acc.x, 0.f) * lw.x + fmaxf(acc.y, 0.f) * lw.y
             + fmaxf(acc.z, 0.f) * lw.z + fmaxf(acc.w, 0.f) * lw.w;
    #pragma unroll
    for (int off = 16; off > 0; off >>= 1)
        pr += __shfl_xor_sync(0xFFFFFFFFu, pr, off);
    if (lane == 0) out[gw] = pr + lin_b[0];
}

// ---------------- launcher ---------------------------------------------------
extern "C" void kernel_launch(void* const* d_in, const int* in_sizes, int n_in,
                              void* d_out, int out_size) {
    const float* x         = (const float*)d_in[0];
    const int*   ei        = (const int*)d_in[1];
    const float* W         = (const float*)d_in[2];
    const float* p         = (const float*)d_in[3];
    const float* w_ih      = (const float*)d_in[4];
    const float* w_hh      = (const float*)d_in[5];
    const float* b_ih      = (const float*)d_in[6];
    const float* b_hh      = (const float*)d_in[7];
    const float* conv_bias = (const float*)d_in[8];
    const float* lin_w     = (const float*)d_in[9];
    const float* lin_b     = (const float*)d_in[10];
    float* out = (float*)d_out;

    k_prep<<<512, 256>>>(p);
    k_scores2<<<(NN * 32 + 255) / 256, 256>>>(x, p, ei);
    k_pick<<<1, 1024>>>();
    k_collect<<<(NN + 255) / 256, 256>>>();
    k_sort<<<1, 256>>>();
    k_gru<<<F, F>>>(x, W, w_ih, w_hh, b_ih, b_hh);
    k_scan1<<<SCAN_BLK, 1024>>>();
    k_scan2<<<1, 32>>>();
    k_scan3<<<(NN + 255) / 256, 256>>>();
    k_fill<<<(NE + 255) / 256, 256>>>(ei);
    k_xw<<<(NN + XROWS - 1) / XROWS, 256, 32768>>>(x);
    k_gather<<<(NN * 32 + 255) / 256, 256>>>(conv_bias, lin_w, lin_b, out);
}